// round 3
// baseline (speedup 1.0000x reference)
#include <cuda_runtime.h>
#include <cuda_bf16.h>

// Problem constants (fixed by the reference setup)
#define N_NODES 150000
#define N_EDGE  2400000
#define DIM     64          // NINP
#define HID     128         // NHID
#define N_TOK   12800       // B*L = 64*200

// ---------------------------------------------------------------------------
// Scratch (device globals; no allocations allowed)
// ---------------------------------------------------------------------------
__device__ __align__(256) float g_dinv[N_NODES];            // deg -> rsqrt(deg) in place
__device__ __align__(256) float g_cvec[N_NODES];            // c = A_hat * 1
__device__ __align__(256) int   g_flag[N_NODES];            // needed-node bitmap
__device__ __align__(256) float g_Y[(size_t)N_NODES * DIM]; // A_hat * emb
__device__ __align__(256) float g_Z[(size_t)N_NODES * DIM]; // A_hat^2 * emb (flagged rows only)
__device__ __align__(256) float g_W[DIM * DIM];             // W1 @ W2
__device__ __align__(256) float g_bW[DIM];                  // b1 @ W2

// Vectorized global reduction (sm_90+): 4 floats per atomic op.
__device__ __forceinline__ void red_add_v4(float* addr, float4 v) {
    asm volatile(
        "{\n\t"
        ".reg .u64 p;\n\t"
        "cvta.to.global.u64 p, %0;\n\t"
        "red.global.add.v4.f32 [p], {%1, %2, %3, %4};\n\t"
        "}"
        :: "l"(addr), "f"(v.x), "f"(v.y), "f"(v.z), "f"(v.w)
        : "memory");
}

// ---------------------------------------------------------------------------
// K0: per-node state init (must run every launch — graph replays)
// ---------------------------------------------------------------------------
__global__ void k_init(void) {
    int i = blockIdx.x * blockDim.x + threadIdx.x;
    if (i >= N_NODES) return;
    g_dinv[i] = 1.0f;   // deg starts at 1 (self loop)
    g_cvec[i] = 0.0f;
    g_flag[i] = 0;
}

// ---------------------------------------------------------------------------
// K1: W = W1 @ W2  (64x128 @ 128x64), bW = b1 @ W2. One block.
// ---------------------------------------------------------------------------
__global__ void k_weights(const float* __restrict__ W1, const float* __restrict__ b1,
                          const float* __restrict__ W2) {
    int tid = threadIdx.x;  // 256 threads
    for (int idx = tid; idx < DIM * DIM; idx += 256) {
        int i = idx >> 6, j = idx & 63;
        float s = 0.0f;
        #pragma unroll 8
        for (int m = 0; m < HID; m++) s += W1[i * HID + m] * W2[m * DIM + j];
        g_W[idx] = s;
    }
    if (tid < DIM) {
        float s = 0.0f;
        #pragma unroll 8
        for (int m = 0; m < HID; m++) s += b1[m] * W2[m * DIM + tid];
        g_bW[tid] = s;
    }
}

// ---------------------------------------------------------------------------
// K2: in-degree accumulation (deg[dst] += 1)
// ---------------------------------------------------------------------------
__global__ void k_deg(const int* __restrict__ ei) {
    int e = blockIdx.x * blockDim.x + threadIdx.x;
    if (e >= N_EDGE) return;
    int dst = ei[N_EDGE + e];
    atomicAdd(&g_dinv[dst], 1.0f);
}

// K3: dinv = rsqrt(deg), in place
__global__ void k_dinv(void) {
    int i = blockIdx.x * blockDim.x + threadIdx.x;
    if (i >= N_NODES) return;
    g_dinv[i] = rsqrtf(g_dinv[i]);
}

// K4: mark needed output nodes
__global__ void k_flag(const int* __restrict__ inp) {
    int t = blockIdx.x * blockDim.x + threadIdx.x;
    if (t >= N_TOK) return;
    g_flag[inp[t]] = 1;
}

// ---------------------------------------------------------------------------
// K5: self-loop init for pass 1: Y[i] = emb[i] * dinv[i]^2 ; cvec[i] = dinv^2
// One thread per float4 (16 per node).
// ---------------------------------------------------------------------------
__global__ void k_self1(const float* __restrict__ emb) {
    long long t = (long long)blockIdx.x * blockDim.x + threadIdx.x;
    if (t >= (long long)N_NODES * 16) return;
    int node = (int)(t >> 4);
    int part = (int)(t & 15);
    float di = g_dinv[node];
    float s = di * di;
    float4 v = ((const float4*)emb)[t];
    v.x *= s; v.y *= s; v.z *= s; v.w *= s;
    ((float4*)g_Y)[t] = v;
    if (part == 0) g_cvec[node] = s;
}

// ---------------------------------------------------------------------------
// K6: edge scatter pass 1: Y[dst] += emb[src] * norm ; cvec[dst] += norm
// 16 threads per edge, one float4 each. 2 edges per warp.
// ---------------------------------------------------------------------------
__global__ void k_scatter1(const int* __restrict__ ei, const float* __restrict__ emb) {
    long long t = (long long)blockIdx.x * blockDim.x + threadIdx.x;
    int g = (int)(t >> 4);
    int part = (int)(t & 15);
    int lane = threadIdx.x & 31;
    int srcLane = lane & 16;  // 0 for lanes 0-15, 16 for lanes 16-31

    int src = 0, dst = 0;
    float norm = 0.0f;
    if (part == 0) {
        src = ei[g];
        dst = ei[N_EDGE + g];
        norm = g_dinv[src] * g_dinv[dst];
        atomicAdd(&g_cvec[dst], norm);
    }
    src  = __shfl_sync(0xffffffffu, src,  srcLane);
    dst  = __shfl_sync(0xffffffffu, dst,  srcLane);
    norm = __shfl_sync(0xffffffffu, norm, srcLane);

    float4 v = ((const float4*)(emb + (long long)src * DIM))[part];
    v.x *= norm; v.y *= norm; v.z *= norm; v.w *= norm;
    red_add_v4((float*)(((float4*)(g_Y + (long long)dst * DIM)) + part), v);
}

// ---------------------------------------------------------------------------
// K7: self-loop init for pass 2, flagged rows only: Z[i] = Y[i] * dinv^2
// ---------------------------------------------------------------------------
__global__ void k_self2(void) {
    long long t = (long long)blockIdx.x * blockDim.x + threadIdx.x;
    if (t >= (long long)N_NODES * 16) return;
    int node = (int)(t >> 4);
    if (!g_flag[node]) return;
    float di = g_dinv[node];
    float s = di * di;
    float4 v = ((const float4*)g_Y)[t];
    v.x *= s; v.y *= s; v.z *= s; v.w *= s;
    ((float4*)g_Z)[t] = v;
}

// ---------------------------------------------------------------------------
// K8: edge scatter pass 2, filtered: if flag[dst]: Z[dst] += Y[src] * norm
// ---------------------------------------------------------------------------
__global__ void k_scatter2(const int* __restrict__ ei) {
    long long t = (long long)blockIdx.x * blockDim.x + threadIdx.x;
    int g = (int)(t >> 4);
    int part = (int)(t & 15);
    int lane = threadIdx.x & 31;
    int srcLane = lane & 16;

    int src = 0, dst = 0, act = 0;
    float norm = 0.0f;
    if (part == 0) {
        dst = ei[N_EDGE + g];
        act = g_flag[dst];
        if (act) {
            src = ei[g];
            norm = g_dinv[src] * g_dinv[dst];
        }
    }
    act  = __shfl_sync(0xffffffffu, act,  srcLane);
    src  = __shfl_sync(0xffffffffu, src,  srcLane);
    dst  = __shfl_sync(0xffffffffu, dst,  srcLane);
    norm = __shfl_sync(0xffffffffu, norm, srcLane);
    if (!act) return;

    float4 v = ((const float4*)(g_Y + (long long)src * DIM))[part];
    v.x *= norm; v.y *= norm; v.z *= norm; v.w *= norm;
    red_add_v4((float*)(((float4*)(g_Z + (long long)dst * DIM)) + part), v);
}

// ---------------------------------------------------------------------------
// K9: final — out[t] = Z[idx_t] @ W + cvec[idx_t]*bW + b2
// 4 tokens per 256-thread block; W staged in shared memory.
// ---------------------------------------------------------------------------
__global__ void k_final(const int* __restrict__ inp, const float* __restrict__ b2,
                        float* __restrict__ out) {
    __shared__ float Ws[DIM * DIM];
    __shared__ float Zs[4 * DIM];
    __shared__ float cs[4];

    int tid = threadIdx.x;
    int grp = tid >> 6;       // token within block (0..3)
    int j   = tid & 63;       // output column

    for (int idx = tid; idx < DIM * DIM; idx += 256) Ws[idx] = g_W[idx];

    int tok = blockIdx.x * 4 + grp;
    int node = inp[tok];
    Zs[grp * DIM + j] = g_Z[(long long)node * DIM + j];
    if (j == 0) cs[grp] = g_cvec[node];
    __syncthreads();

    float acc = cs[grp] * g_bW[j] + b2[j];
    #pragma unroll 16
    for (int k = 0; k < DIM; k++)
        acc += Zs[grp * DIM + k] * Ws[k * DIM + j];
    out[(long long)tok * DIM + j] = acc;
}

// ---------------------------------------------------------------------------
// Launcher
// Input order (metadata): 0 emb, 1 W1, 2 b1, 3 W2, 4 b2,
//                         5 input, 6 input_timestamp (unused), 7 edge_index
// NOTE: index tensors are int32 (JAX x64 disabled -> astype(int64) is a no-op).
// ---------------------------------------------------------------------------
extern "C" void kernel_launch(void* const* d_in, const int* in_sizes, int n_in,
                              void* d_out, int out_size) {
    const float* emb = (const float*)d_in[0];
    const float* W1  = (const float*)d_in[1];
    const float* b1  = (const float*)d_in[2];
    const float* W2  = (const float*)d_in[3];
    const float* b2  = (const float*)d_in[4];
    const int*   inp = (const int*)d_in[5];
    const int*   ei  = (const int*)d_in[7];
    float* out = (float*)d_out;

    const int T = 256;
    int nodeBlocks  = (N_NODES + T - 1) / T;              // 586
    int edgeBlocks  = (N_EDGE + T - 1) / T;               // 9375
    int node16Blk   = (int)(((long long)N_NODES * 16 + T - 1) / T);  // 9375
    int edge16Blk   = (int)(((long long)N_EDGE * 16) / T);           // 150000 exact

    k_init<<<nodeBlocks, T>>>();
    k_weights<<<1, T>>>(W1, b1, W2);
    k_deg<<<edgeBlocks, T>>>(ei);
    k_dinv<<<nodeBlocks, T>>>();
    k_flag<<<(N_TOK + T - 1) / T, T>>>(inp);
    k_self1<<<node16Blk, T>>>(emb);
    k_scatter1<<<edge16Blk, T>>>(ei, emb);
    k_self2<<<node16Blk, T>>>();
    k_scatter2<<<edge16Blk, T>>>(ei);
    k_final<<<N_TOK / 4, T>>>(inp, b2, out);
}

// round 4
// speedup vs baseline: 1.7851x; 1.7851x over previous
#include <cuda_runtime.h>
#include <cuda_bf16.h>

// Problem constants (fixed by the reference setup)
#define N_NODES 150000
#define N_EDGE  2400000
#define DIM     64          // NINP
#define HID     128         // NHID
#define N_TOK   12800       // B*L = 64*200
#define NB1024  ((N_NODES + 1023) / 1024)   // 147 scan blocks

// ---------------------------------------------------------------------------
// Scratch (device globals; no allocations allowed)
// ---------------------------------------------------------------------------
__device__ __align__(256) int   g_count[N_NODES];     // in-degree (histogram)
__device__ __align__(256) int   g_rowstart[N_NODES];  // CSR row offsets (exclusive scan)
__device__ __align__(256) int   g_cursor[N_NODES];    // bucket cursors for build
__device__ __align__(256) int   g_bsum[NB1024];       // scan block sums
__device__ __align__(256) int   g_boff[NB1024];       // scanned block offsets
__device__ __align__(256) int   g_csrc[N_EDGE];       // CSR src indices, grouped by dst
__device__ __align__(256) float g_dinv[N_NODES];      // rsqrt(deg+1)
__device__ __align__(256) float g_cvec[N_NODES];      // c = A_hat * 1 (row sums)
__device__ __align__(256) int   g_flag[N_NODES];      // output-node bitmap
__device__ __align__(256) int   g_need[N_NODES];      // nodes whose Y row is consumed
__device__ __align__(256) float g_Y[(size_t)N_NODES * DIM]; // A_hat * emb   (need rows)
__device__ __align__(256) float g_Z[(size_t)N_NODES * DIM]; // A_hat^2 * emb (flag rows)
__device__ __align__(256) float g_W[DIM * DIM];       // W1 @ W2
__device__ __align__(256) float g_bW[DIM];            // b1 @ W2

// ---------------------------------------------------------------------------
// K0: zero per-node state (graph replays -> must reset every launch)
// ---------------------------------------------------------------------------
__global__ void k_init(void) {
    int i = blockIdx.x * blockDim.x + threadIdx.x;
    if (i >= N_NODES) return;
    g_count[i] = 0;
    g_flag[i]  = 0;
    g_need[i]  = 0;
}

// ---------------------------------------------------------------------------
// K1: W = W1 @ W2, bW = b1 @ W2. One block.
// ---------------------------------------------------------------------------
__global__ void k_weights(const float* __restrict__ W1, const float* __restrict__ b1,
                          const float* __restrict__ W2) {
    int tid = threadIdx.x;  // 256 threads
    for (int idx = tid; idx < DIM * DIM; idx += 256) {
        int i = idx >> 6, j = idx & 63;
        float s = 0.0f;
        #pragma unroll 8
        for (int m = 0; m < HID; m++) s += W1[i * HID + m] * W2[m * DIM + j];
        g_W[idx] = s;
    }
    if (tid < DIM) {
        float s = 0.0f;
        #pragma unroll 8
        for (int m = 0; m < HID; m++) s += b1[m] * W2[m * DIM + tid];
        g_bW[tid] = s;
    }
}

// ---------------------------------------------------------------------------
// K2: in-degree histogram (int)
// ---------------------------------------------------------------------------
__global__ void k_hist(const int* __restrict__ ei) {
    int e = blockIdx.x * blockDim.x + threadIdx.x;
    if (e >= N_EDGE) return;
    atomicAdd(&g_count[ei[N_EDGE + e]], 1);
}

// K3: mark output nodes
__global__ void k_flag(const int* __restrict__ inp) {
    int t = blockIdx.x * blockDim.x + threadIdx.x;
    if (t >= N_TOK) return;
    g_flag[inp[t]] = 1;
}

// ---------------------------------------------------------------------------
// K4: per-block exclusive scan of g_count (1024 elems / block, 4 per thread)
// ---------------------------------------------------------------------------
__global__ void k_scan_local(void) {
    __shared__ int sh[256];
    int tid = threadIdx.x;
    int base = blockIdx.x * 1024 + tid * 4;

    int c[4], ts = 0;
    #pragma unroll
    for (int k = 0; k < 4; k++) {
        int i = base + k;
        c[k] = (i < N_NODES) ? g_count[i] : 0;
        ts += c[k];
    }
    sh[tid] = ts;
    __syncthreads();
    for (int off = 1; off < 256; off <<= 1) {
        int v = (tid >= off) ? sh[tid - off] : 0;
        __syncthreads();
        sh[tid] += v;
        __syncthreads();
    }
    int run = sh[tid] - ts;   // exclusive prefix of this thread's chunk
    #pragma unroll
    for (int k = 0; k < 4; k++) {
        int i = base + k;
        if (i < N_NODES) g_rowstart[i] = run;
        run += c[k];
    }
    if (tid == 255) g_bsum[blockIdx.x] = sh[255];
}

// K5: exclusive scan of the 147 block sums (one block)
__global__ void k_scan_bsum(void) {
    __shared__ int sh[256];
    int tid = threadIdx.x;
    int v = (tid < NB1024) ? g_bsum[tid] : 0;
    int orig = v;
    sh[tid] = v;
    __syncthreads();
    for (int off = 1; off < 256; off <<= 1) {
        int w = (tid >= off) ? sh[tid - off] : 0;
        __syncthreads();
        sh[tid] += w;
        __syncthreads();
    }
    if (tid < NB1024) g_boff[tid] = sh[tid] - orig;
}

// K6: finalize rowstart, set cursors, compute dinv = rsqrt(deg+1)
__global__ void k_scan_add(void) {
    int i = blockIdx.x * blockDim.x + threadIdx.x;
    if (i >= N_NODES) return;
    int rs = g_rowstart[i] + g_boff[i >> 10];
    g_rowstart[i] = rs;
    g_cursor[i]   = rs;
    g_dinv[i]     = rsqrtf((float)g_count[i] + 1.0f);
}

// ---------------------------------------------------------------------------
// K7: CSR build — scatter src into per-dst buckets
// ---------------------------------------------------------------------------
__global__ void k_build(const int* __restrict__ ei) {
    int e = blockIdx.x * blockDim.x + threadIdx.x;
    if (e >= N_EDGE) return;
    int src = ei[e];
    int dst = ei[N_EDGE + e];
    int pos = atomicAdd(&g_cursor[dst], 1);
    g_csrc[pos] = src;
}

// ---------------------------------------------------------------------------
// K8: need = flag ∪ { src of edges into flagged nodes }. Warp per node.
// ---------------------------------------------------------------------------
__global__ void k_need(void) {
    int warp = (blockIdx.x * blockDim.x + threadIdx.x) >> 5;
    int lane = threadIdx.x & 31;
    if (warp >= N_NODES) return;
    if (!g_flag[warp]) return;
    if (lane == 0) g_need[warp] = 1;
    int rs  = g_rowstart[warp];
    int cnt = g_count[warp];
    for (int e = lane; e < cnt; e += 32)
        g_need[g_csrc[rs + e]] = 1;
}

// ---------------------------------------------------------------------------
// K9: gather pass 1 (needed rows only):
//   Y[i] = dinv_i^2 * emb[i] + sum_{src->i} dinv_src*dinv_i * emb[src]
//   cvec[i] = dinv_i^2 + sum dinv_src*dinv_i
// One warp per node; lane owns 2 columns (float2).
// ---------------------------------------------------------------------------
__global__ void k_gather1(const float* __restrict__ emb) {
    int node = (blockIdx.x * blockDim.x + threadIdx.x) >> 5;
    int lane = threadIdx.x & 31;
    if (node >= N_NODES) return;
    if (!g_need[node]) return;

    int rs  = g_rowstart[node];
    int cnt = g_count[node];
    float di = g_dinv[node];
    float s  = di * di;

    float2 e0 = ((const float2*)(emb + (size_t)node * DIM))[lane];
    float2 acc = make_float2(e0.x * s, e0.y * s);
    float  csum = s;

    int e = 0;
    for (; e + 2 <= cnt; e += 2) {
        int s0 = __ldg(&g_csrc[rs + e]);
        int s1 = __ldg(&g_csrc[rs + e + 1]);
        float w0 = g_dinv[s0] * di;
        float w1 = g_dinv[s1] * di;
        float2 v0 = ((const float2*)(emb + (size_t)s0 * DIM))[lane];
        float2 v1 = ((const float2*)(emb + (size_t)s1 * DIM))[lane];
        acc.x += v0.x * w0 + v1.x * w1;
        acc.y += v0.y * w0 + v1.y * w1;
        csum  += w0 + w1;
    }
    if (e < cnt) {
        int s0 = __ldg(&g_csrc[rs + e]);
        float w0 = g_dinv[s0] * di;
        float2 v0 = ((const float2*)(emb + (size_t)s0 * DIM))[lane];
        acc.x += v0.x * w0;
        acc.y += v0.y * w0;
        csum  += w0;
    }

    ((float2*)(g_Y + (size_t)node * DIM))[lane] = acc;
    if (lane == 0) g_cvec[node] = csum;
}

// ---------------------------------------------------------------------------
// K10: gather pass 2 (flagged rows only): Z = A_hat * Y
// ---------------------------------------------------------------------------
__global__ void k_gather2(void) {
    int node = (blockIdx.x * blockDim.x + threadIdx.x) >> 5;
    int lane = threadIdx.x & 31;
    if (node >= N_NODES) return;
    if (!g_flag[node]) return;

    int rs  = g_rowstart[node];
    int cnt = g_count[node];
    float di = g_dinv[node];
    float s  = di * di;

    float2 y0 = ((const float2*)(g_Y + (size_t)node * DIM))[lane];
    float2 acc = make_float2(y0.x * s, y0.y * s);

    int e = 0;
    for (; e + 2 <= cnt; e += 2) {
        int s0 = __ldg(&g_csrc[rs + e]);
        int s1 = __ldg(&g_csrc[rs + e + 1]);
        float w0 = g_dinv[s0] * di;
        float w1 = g_dinv[s1] * di;
        float2 v0 = ((const float2*)(g_Y + (size_t)s0 * DIM))[lane];
        float2 v1 = ((const float2*)(g_Y + (size_t)s1 * DIM))[lane];
        acc.x += v0.x * w0 + v1.x * w1;
        acc.y += v0.y * w0 + v1.y * w1;
    }
    if (e < cnt) {
        int s0 = __ldg(&g_csrc[rs + e]);
        float w0 = g_dinv[s0] * di;
        float2 v0 = ((const float2*)(g_Y + (size_t)s0 * DIM))[lane];
        acc.x += v0.x * w0;
        acc.y += v0.y * w0;
    }

    ((float2*)(g_Z + (size_t)node * DIM))[lane] = acc;
}

// ---------------------------------------------------------------------------
// K11: final — out[t] = Z[idx_t] @ W + cvec[idx_t]*bW + b2
// 4 tokens per 256-thread block; W staged in shared memory.
// ---------------------------------------------------------------------------
__global__ void k_final(const int* __restrict__ inp, const float* __restrict__ b2,
                        float* __restrict__ out) {
    __shared__ float Ws[DIM * DIM];
    __shared__ float Zs[4 * DIM];
    __shared__ float cs[4];

    int tid = threadIdx.x;
    int grp = tid >> 6;       // token within block (0..3)
    int j   = tid & 63;       // output column

    for (int idx = tid; idx < DIM * DIM; idx += 256) Ws[idx] = g_W[idx];

    int tok = blockIdx.x * 4 + grp;
    int node = inp[tok];
    Zs[grp * DIM + j] = g_Z[(size_t)node * DIM + j];
    if (j == 0) cs[grp] = g_cvec[node];
    __syncthreads();

    float acc = cs[grp] * g_bW[j] + b2[j];
    #pragma unroll 16
    for (int k = 0; k < DIM; k++)
        acc += Zs[grp * DIM + k] * Ws[k * DIM + j];
    out[(size_t)tok * DIM + j] = acc;
}

// ---------------------------------------------------------------------------
// Launcher
// Input order (metadata): 0 emb, 1 W1, 2 b1, 3 W2, 4 b2,
//                         5 input, 6 input_timestamp (unused), 7 edge_index
// NOTE: index tensors are int32 (JAX x64 disabled -> astype(int64) is a no-op).
// ---------------------------------------------------------------------------
extern "C" void kernel_launch(void* const* d_in, const int* in_sizes, int n_in,
                              void* d_out, int out_size) {
    const float* emb = (const float*)d_in[0];
    const float* W1  = (const float*)d_in[1];
    const float* b1  = (const float*)d_in[2];
    const float* W2  = (const float*)d_in[3];
    const float* b2  = (const float*)d_in[4];
    const int*   inp = (const int*)d_in[5];
    const int*   ei  = (const int*)d_in[7];
    float* out = (float*)d_out;

    const int T = 256;
    int nodeBlocks = (N_NODES + T - 1) / T;                 // 586
    int edgeBlocks = (N_EDGE + T - 1) / T;                  // 9375
    int warpBlocks = (N_NODES + (T / 32) - 1) / (T / 32);   // 18750 (warp per node)

    k_init<<<nodeBlocks, T>>>();
    k_weights<<<1, T>>>(W1, b1, W2);
    k_hist<<<edgeBlocks, T>>>(ei);
    k_flag<<<(N_TOK + T - 1) / T, T>>>(inp);
    k_scan_local<<<NB1024, T>>>();
    k_scan_bsum<<<1, T>>>();
    k_scan_add<<<nodeBlocks, T>>>();
    k_build<<<edgeBlocks, T>>>(ei);
    k_need<<<warpBlocks, T>>>();
    k_gather1<<<warpBlocks, T>>>(emb);
    k_gather2<<<warpBlocks, T>>>();
    k_final<<<N_TOK / 4, T>>>(inp, b2, out);
}